// round 14
// baseline (speedup 1.0000x reference)
#include <cuda_runtime.h>
#include <cuda_fp16.h>
#include <math.h>

// ---------------- problem constants ----------------
#define L_    2
#define B_    32
#define T_    16
#define H_    1024
#define NCTA  128           // 32 gate rows per CTA (8 units x 4 gates)
#define ROWS  32
#define NTHREADS 256
#define RET_ELEMS (B_*T_*H_)

// Each warp owns a 128-k slice of BOTH the x-half and the h-half (8 k16-steps each).
// l0 weights: RF fragments (x + h = 128 regs). l1 weights: SMEM (x chunks 0-7, h 8-15).

// smem layout (bytes)
#define SM_W1   0                       // 8 warps * 16KB resident layer-1 W = 131072
#define SM_STG  131072                  // 8 * 5 * 1280 = 51200 (5-buffer staging)
#define SM_PART 182272                  // 8 * 4224 = 33792 (dedicated partials)
#define SM_C    216064                  // 2048
#define SM_H    218112                  // 2048
#define SM_R    220160                  // 1024
#define SMEM_TOTAL 221184

// ---------------- device globals (scratch; no allocs) ----------------
__device__ __half  g_xin[2][H_][B_];          // chain input, parity by n
__device__ __half  g_hst[2][L_][H_][B_];      // per-layer h state, parity by t
__device__ float   g_losspart[NCTA];
__device__ unsigned g_bar;

// ---------------- helpers ----------------
__device__ __forceinline__ unsigned su(const void* p) {
    return (unsigned)__cvta_generic_to_shared(p);
}
__device__ __forceinline__ void cp16(unsigned d, const void* s) {
    asm volatile("cp.async.cg.shared.global [%0], [%1], 16;\n" :: "r"(d), "l"(s));
}
__device__ __forceinline__ void cpcommit() { asm volatile("cp.async.commit_group;\n"); }
template <int N>
__device__ __forceinline__ void cpwaitN() { asm volatile("cp.async.wait_group %0;\n" :: "n"(N)); }

__device__ __forceinline__ void ldsm4(unsigned* r, unsigned a) {
    asm volatile("ldmatrix.sync.aligned.m8n8.x4.shared.b16 {%0,%1,%2,%3}, [%4];\n"
                 : "=r"(r[0]), "=r"(r[1]), "=r"(r[2]), "=r"(r[3]) : "r"(a));
}
__device__ __forceinline__ void ldsm4t(unsigned* r, unsigned a) {
    asm volatile("ldmatrix.sync.aligned.m8n8.x4.trans.shared.b16 {%0,%1,%2,%3}, [%4];\n"
                 : "=r"(r[0]), "=r"(r[1]), "=r"(r[2]), "=r"(r[3]) : "r"(a));
}
__device__ __forceinline__ void mma16816(float* c, const unsigned* a, const unsigned* b) {
    asm volatile("mma.sync.aligned.m16n8k16.row.col.f32.f16.f16.f32 "
                 "{%0,%1,%2,%3}, {%4,%5,%6,%7}, {%8,%9}, {%0,%1,%2,%3};\n"
                 : "+f"(c[0]), "+f"(c[1]), "+f"(c[2]), "+f"(c[3])
                 : "r"(a[0]), "r"(a[1]), "r"(a[2]), "r"(a[3]), "r"(b[0]), "r"(b[1]));
}
__device__ __forceinline__ float sigm(float v) { return 1.f / (1.f + __expf(-v)); }

__device__ __forceinline__ void bar_acquire_ld(unsigned* v) {
    asm volatile("ld.acquire.gpu.global.u32 %0, [%1];" : "=r"(*v) : "l"(&g_bar));
}

// convert one 32row x 128k slice into 8 swizzled 1KB chunks:
// chunk s: row i at byte i*32 + ((hf ^ ((i>>2)&1))*16, k = s*16 + hf*8
__device__ __forceinline__ void conv_mat(const float* __restrict__ Wsrc, int m, int kb,
                                         char* dst, int lane) {
    int srow = (lane >> 3) * 1024 + m * 8 + (lane & 7);
    const float* s0 = Wsrc + (long)srow * 1024 + kb;
    const int sw = (lane >> 2) & 1;
#pragma unroll
    for (int s = 0; s < 8; s++) {
#pragma unroll
        for (int hf = 0; hf < 2; hf++) {
            const float* src = s0 + s * 16 + hf * 8;
            float4 f0 = ((const float4*)src)[0];
            float4 f1 = ((const float4*)src)[1];
            __half2 p0 = __floats2half2_rn(f0.x, f0.y);
            __half2 p1 = __floats2half2_rn(f0.z, f0.w);
            __half2 p2 = __floats2half2_rn(f1.x, f1.y);
            __half2 p3 = __floats2half2_rn(f1.z, f1.w);
            uint4 u;
            u.x = *reinterpret_cast<unsigned*>(&p0);
            u.y = *reinterpret_cast<unsigned*>(&p1);
            u.z = *reinterpret_cast<unsigned*>(&p2);
            u.w = *reinterpret_cast<unsigned*>(&p3);
            *reinterpret_cast<uint4*>(dst + s * 1024 + lane * 32 + ((hf ^ sw) * 16)) = u;
        }
    }
}

// ---- phase prefill: stages 0..3 into buffers 0..3 (4 commit groups) ----
__device__ __forceinline__ void phase_prefill(unsigned stgsu, const __half* xsrc, int lane) {
#pragma unroll
    for (int st = 0; st < 4; st++) {
#pragma unroll
        for (int j = 0; j < 2; j++) {
            int e = lane + 32 * j, r = e >> 2, sg = e & 3;
            cp16(stgsu + st * 1280 + r * 80 + sg * 16, xsrc + (st * 16 + r) * 32 + sg * 8);
        }
        cpcommit();
    }
}

// ---- phase main, A from RF fragments (layer 0) ----
__device__ __forceinline__ void phase_main_rf(
    unsigned stgsu, const __half* xsrc,
    const unsigned aF0[8][4], const unsigned aF1[8][4],
    float acc0[4][4], float acc1[4][4], int lane, int aRow, int aCol) {
    cpwaitN<3>();
    __syncwarp();
    unsigned bc0[4], bc1[4];
    {
        unsigned xB = stgsu + aRow * 80 + aCol * 2;
        ldsm4t(bc0, xB); ldsm4t(bc1, xB + 32);
    }
#pragma unroll
    for (int s = 0; s < 8; s++) {
        const int sp = s + 4;
        if (sp < 8) {
#pragma unroll
            for (int j = 0; j < 2; j++) {
                int e = lane + 32 * j, r = e >> 2, sg = e & 3;
                cp16(stgsu + (sp % 5) * 1280 + r * 80 + sg * 16,
                     xsrc + (sp * 16 + r) * 32 + sg * 8);
            }
        }
        cpcommit();
        mma16816(acc0[0], aF0[s], bc0 + 0); mma16816(acc0[1], aF0[s], bc0 + 2);
        mma16816(acc0[2], aF0[s], bc1 + 0); mma16816(acc0[3], aF0[s], bc1 + 2);
        mma16816(acc1[0], aF1[s], bc0 + 0); mma16816(acc1[1], aF1[s], bc0 + 2);
        mma16816(acc1[2], aF1[s], bc1 + 0); mma16816(acc1[3], aF1[s], bc1 + 2);
        if (s < 7) {
            cpwaitN<3>();
            __syncwarp();
            unsigned xB = stgsu + ((s + 1) % 5) * 1280 + aRow * 80 + aCol * 2;
            ldsm4t(bc0, xB); ldsm4t(bc1, xB + 32);
        } else {
            cpwaitN<3>();     // keep pending <= 3 at phase exit
            __syncwarp();
        }
    }
}

// ---- phase main, A from resident SMEM chunks (layer 1) ----
__device__ __forceinline__ void phase_main_sm(
    unsigned stgsu, const __half* xsrc, unsigned w1su, int choff,
    float acc0[4][4], float acc1[4][4], int lane, int aRow, int aCol, int aSel16) {
    cpwaitN<3>();
    __syncwarp();
    unsigned bc0[4], bc1[4], ac0[4], ac1[4];
    {
        unsigned xB = stgsu + aRow * 80 + aCol * 2;
        ldsm4t(bc0, xB); ldsm4t(bc1, xB + 32);
        unsigned aB = w1su + choff * 1024 + aRow * 32 + aSel16;
        ldsm4(ac0, aB); ldsm4(ac1, aB + 512);
    }
#pragma unroll
    for (int s = 0; s < 8; s++) {
        const int sp = s + 4;
        if (sp < 8) {
#pragma unroll
            for (int j = 0; j < 2; j++) {
                int e = lane + 32 * j, r = e >> 2, sg = e & 3;
                cp16(stgsu + (sp % 5) * 1280 + r * 80 + sg * 16,
                     xsrc + (sp * 16 + r) * 32 + sg * 8);
            }
        }
        cpcommit();
        mma16816(acc0[0], ac0, bc0 + 0); mma16816(acc0[1], ac0, bc0 + 2);
        mma16816(acc0[2], ac0, bc1 + 0); mma16816(acc0[3], ac0, bc1 + 2);
        mma16816(acc1[0], ac1, bc0 + 0); mma16816(acc1[1], ac1, bc0 + 2);
        mma16816(acc1[2], ac1, bc1 + 0); mma16816(acc1[3], ac1, bc1 + 2);
        if (s < 7) {
            cpwaitN<3>();
            __syncwarp();
            unsigned xB = stgsu + ((s + 1) % 5) * 1280 + aRow * 80 + aCol * 2;
            ldsm4t(bc0, xB); ldsm4t(bc1, xB + 32);
            unsigned aB = w1su + (choff + s + 1) * 1024 + aRow * 32 + aSel16;
            ldsm4(ac0, aB); ldsm4(ac1, aB + 512);
        } else {
            cpwaitN<3>();
            __syncwarp();
        }
    }
}

// ---------------- prep: state transposes + counter reset ----------------
__global__ void prep(const float* __restrict__ x, const float* __restrict__ h0) {
    long tid0 = (long)blockIdx.x * blockDim.x + threadIdx.x;
    long stride = (long)gridDim.x * blockDim.x;
    if (tid0 == 0) g_bar = 0u;
    for (long i = tid0; i < H_ * B_; i += stride) {
        int k = (int)(i >> 5), b = (int)(i & 31);
        g_xin[0][k][b] = __float2half(x[b * H_ + k]);
    }
    for (long i = tid0; i < (long)L_ * H_ * B_; i += stride) {
        int b = (int)(i & 31), k = (int)((i >> 5) & 1023), l = (int)(i >> 15);
        g_hst[0][l][k][b] = __float2half(h0[(l * B_ + b) * H_ + k]);
    }
}

// ---------------- persistent LSTM kernel ----------------
__global__ void __launch_bounds__(NTHREADS, 1)
lstm_kernel(const float* __restrict__ c0, const float* __restrict__ h0,
            const float* __restrict__ h_mask, const float* __restrict__ c_mask,
            const float* __restrict__ labels,
            const float* __restrict__ W_ih, const float* __restrict__ W_hh,
            const float* __restrict__ b_ih, const float* __restrict__ b_hh,
            float* __restrict__ out, int write_loss) {
    const int m = blockIdx.x, tid = threadIdx.x;
    const int w = tid >> 5, lane = tid & 31;

    extern __shared__ char sm_[];
    float* cst  = (float*)(sm_ + SM_C);
    float* hst  = (float*)(sm_ + SM_H);
    float* red  = (float*)(sm_ + SM_R);
    char*  W1w  = sm_ + SM_W1 + w * 16384;   // l1 resident: x chunks 0-7, h chunks 8-15
    char*  STGw = sm_ + SM_STG + w * 6400;   // 5-buffer staging
    float* partw = (float*)(sm_ + SM_PART + w * 4224);

    // exact fp32 state init for this CTA's 8 units, both layers
    for (int i = tid; i < 2 * 8 * 32; i += NTHREADS) {
        int l = i >> 8, u = (i >> 5) & 7, b = i & 31;
        int guu = m * 8 + u;
        cst[i] = c0[(l * B_ + b) * H_ + guu];
        hst[i] = h0[(l * B_ + b) * H_ + guu];
    }

    // bias regs for thread's unit (u = w): br[l][gate]
    float br[2][4];
#pragma unroll
    for (int l = 0; l < 2; l++)
#pragma unroll
        for (int g = 0; g < 4; g++) {
            int idx = l * 4096 + g * 1024 + m * 8 + w;
            br[l][g] = b_ih[idx] + b_hh[idx];
        }

    const int kb = w * 128;                  // warp's k-slice start (within each half)
    const int aRow = lane & 15, aCol = (lane >> 4) * 8;
    const int aSel16 = ((lane >> 4) ^ ((aRow >> 2) & 1)) * 16;
    const unsigned w1su  = su(W1w);
    const unsigned stgsu = su(STGw);

    // ---- weight conversion: l0 x/h -> RF fragments, l1 x/h -> resident SMEM ----
    unsigned aWx0[8][4], aWx1[8][4], aWh0[8][4], aWh1[8][4];
    conv_mat(W_ih, m, kb, W1w, lane);
    __syncwarp();
#pragma unroll
    for (int c = 0; c < 8; c++) {
        unsigned aB = w1su + c * 1024 + aRow * 32 + aSel16;
        ldsm4(aWx0[c], aB); ldsm4(aWx1[c], aB + 512);
    }
    __syncwarp();
    conv_mat(W_hh, m, kb, W1w, lane);
    __syncwarp();
#pragma unroll
    for (int c = 0; c < 8; c++) {
        unsigned aB = w1su + c * 1024 + aRow * 32 + aSel16;
        ldsm4(aWh0[c], aB); ldsm4(aWh1[c], aB + 512);
    }
    __syncwarp();
    conv_mat(W_ih + 4096 * 1024, m, kb, W1w, lane);          // l1 x -> chunks 0-7
    conv_mat(W_hh + 4096 * 1024, m, kb, W1w + 8192, lane);   // l1 h -> chunks 8-15
    __syncthreads();

    float lossacc = 0.f;

    // prefill h-phase stages for cell 0 (h0 state from prep)
    phase_prefill(stgsu, &g_hst[0][0][kb][0], lane);

    for (int n = 0; n < T_ * L_; n++) {
        const int t = n >> 1, l = n & 1;

        // mask/label prefetch (u=w, b=lane) — off critical path
        const int gu = m * 8 + w;
        const long mo = ((long)(n * B_ + lane)) * H_ + gu;
        const float hmv = __ldg(h_mask + mo);
        const float cmv = __ldg(c_mask + mo);
        float labv = 0.f;
        long ro = 0;
        if (l == 1) {
            ro = ((long)(lane * T_ + t)) * H_ + gu;
            labv = __ldg(labels + ro);
        }

        float acc0[4][4], acc1[4][4];
#pragma unroll
        for (int j = 0; j < 4; j++)
#pragma unroll
            for (int q = 0; q < 4; q++) { acc0[j][q] = 0.f; acc1[j][q] = 0.f; }

        // ---- h-phase (input published 2 cells ago; runs while flag propagates) ----
        const __half* hsrc = &g_hst[t & 1][l][kb][0];
        if (l == 0)
            phase_main_rf(stgsu, hsrc, aWh0, aWh1, acc0, acc1, lane, aRow, aCol);
        else
            phase_main_sm(stgsu, hsrc, w1su, 8, acc0, acc1, lane, aRow, aCol, aSel16);

        // ---- wait for flag(n-1): x input published by previous cell ----
        if (n) {
            const unsigned need = (unsigned)n * NCTA;
            if (lane == 0) {
                unsigned v;
                do { bar_acquire_ld(&v); } while (v < need);
            }
            __syncwarp();
            unsigned v2;
            bar_acquire_ld(&v2);     // per-lane acquire for ordering
        }

        // ---- x-phase ----
        const __half* xsrc = &g_xin[n & 1][kb][0];
        phase_prefill(stgsu, xsrc, lane);
        if (l == 0)
            phase_main_rf(stgsu, xsrc, aWx0, aWx1, acc0, acc1, lane, aRow, aCol);
        else
            phase_main_sm(stgsu, xsrc, w1su, 0, acc0, acc1, lane, aRow, aCol, aSel16);

        // ---- prefill h-phase stages for cell n+1 (hides under epilogue) ----
        if (n + 1 < T_ * L_) {
            const int t1 = (n + 1) >> 1, l1v = (n + 1) & 1;
            phase_prefill(stgsu, &g_hst[t1 & 1][l1v][kb][0], lane);
        }

        // ---- partials: dedicated warp region (full 32 rows per warp) ----
#pragma unroll
        for (int f = 0; f < 2; f++) {
            float (*ac)[4] = f ? acc1 : acc0;
#pragma unroll
            for (int j = 0; j < 4; j++) {
                int r0 = f * 16 + (lane >> 2), col = j * 8 + (lane & 3) * 2;
                partw[r0 * 33 + col]           = ac[j][0];
                partw[r0 * 33 + col + 1]       = ac[j][1];
                partw[(r0 + 8) * 33 + col]     = ac[j][2];
                partw[(r0 + 8) * 33 + col + 1] = ac[j][3];
            }
        }
        __syncthreads();

        // ---- cell math: thread (u=w, b=lane) ----
        {
            float g[4];
#pragma unroll
            for (int gg = 0; gg < 4; gg++) {
                float ssum = 0.f;
#pragma unroll
                for (int ww = 0; ww < 8; ww++)
                    ssum += ((float*)(sm_ + SM_PART + ww * 4224))[(gg * 8 + w) * 33 + lane];
                g[gg] = ssum + br[l][gg];
            }
            const int si = (l * 8 + w) * 32 + lane;
            float cold = cst[si], hold = hst[si];
            float ccand = sigm(g[1]) * cold + sigm(g[0]) * tanhf(g[2]);
            float hcand = sigm(g[3]) * tanhf(ccand);
            float cn = cmv * cold + (1.f - cmv) * ccand;
            float hn = hmv * hold + (1.f - hmv) * hcand;
            cst[si] = cn;
            hst[si] = hn;
            __half hh = __float2half(hn);
            g_xin[(n + 1) & 1][gu][lane] = hh;
            g_hst[(t & 1) ^ 1][l][gu][lane] = hh;
            if (l == 1) {
                out[ro] = hn;
                float d = hn - labv;
                lossacc += d * d;
            }
        }
        __syncthreads();            // partial reads + h stores complete CTA-wide
        if (tid == 0)
            asm volatile("red.release.gpu.global.add.u32 [%0], %1;\n"
                         :: "l"(&g_bar), "r"(1u));
    }

    // ---- deterministic loss reduction ----
    red[tid] = lossacc;
    __syncthreads();
    for (int sft = 128; sft > 0; sft >>= 1) {
        if (tid < sft) red[tid] += red[tid + sft];
        __syncthreads();
    }
    if (tid == 0) {
        g_losspart[m] = red[0];
        asm volatile("red.release.gpu.global.add.u32 [%0], %1;\n"
                     :: "l"(&g_bar), "r"(1u));
        if (m == 0 && write_loss) {
            const unsigned need = (unsigned)(T_ * L_ + 1) * NCTA;
            unsigned v;
            do { bar_acquire_ld(&v); } while (v < need);
            float ssum = 0.f;
            for (int i = 0; i < NCTA; i++) ssum += g_losspart[i];
            out[RET_ELEMS] = ssum / (float)RET_ELEMS;
        }
    }
}

// ---------------- launch ----------------
extern "C" void kernel_launch(void* const* d_in, const int* in_sizes, int n_in,
                              void* d_out, int out_size) {
    const float* x      = (const float*)d_in[0];
    const float* h0     = (const float*)d_in[1];
    const float* c0     = (const float*)d_in[2];
    const float* h_mask = (const float*)d_in[3];
    const float* c_mask = (const float*)d_in[4];
    const float* labels = (const float*)d_in[5];
    const float* W_ih   = (const float*)d_in[6];
    const float* W_hh   = (const float*)d_in[7];
    const float* b_ih   = (const float*)d_in[8];
    const float* b_hh   = (const float*)d_in[9];
    float* out = (float*)d_out;

    cudaFuncSetAttribute(lstm_kernel, cudaFuncAttributeMaxDynamicSharedMemorySize,
                         SMEM_TOTAL);

    prep<<<128, 256>>>(x, h0);
    int write_loss = (out_size > RET_ELEMS) ? 1 : 0;
    lstm_kernel<<<NCTA, NTHREADS, SMEM_TOTAL>>>(c0, h0, h_mask, c_mask, labels,
                                                W_ih, W_hh, b_ih, b_hh, out,
                                                write_loss);
}

// round 15
// speedup vs baseline: 1.0997x; 1.0997x over previous
#include <cuda_runtime.h>
#include <cuda_fp16.h>
#include <math.h>

// ---------------- problem constants ----------------
#define L_    2
#define B_    32
#define T_    16
#define H_    1024
#define K_    2048
#define NCTA  128           // 32 gate rows per CTA (8 units x 4 gates)
#define ROWS  32
#define NTHREADS 256
#define KW    256           // K slice per warp
#define D_    5             // X cp.async pipeline depth (stages of k16)
#define WSTG  6400          // per-warp staging bytes (5 * 1280); partials alias [0,4224)
#define RET_ELEMS (B_*T_*H_)

// smem layout (bytes)
#define SM_W1  0                        // 8 warps * 16KB resident layer-1 W = 131072
#define SM_STG 131072                   // 8 * 6400 = 51200 (stages; warp-local partials alias)
#define SM_W0  182272                   // 8 * 4096 = 32768 (l0 chunks 12..15 per warp)
#define SM_C   215040                   // 2048
#define SM_H   217088                   // 2048
#define SM_R   219136                   // 1024
#define SMEM_TOTAL 220160

// ---------------- device globals (scratch; no allocs) ----------------
__device__ __half  g_xin[2][H_][B_];          // chain input, parity by n
__device__ __half  g_hst[2][L_][H_][B_];      // per-layer h state, parity by t
__device__ float   g_losspart[NCTA];
__device__ unsigned g_bar;

// ---------------- helpers ----------------
__device__ __forceinline__ unsigned su(const void* p) {
    return (unsigned)__cvta_generic_to_shared(p);
}
__device__ __forceinline__ void cp16(unsigned d, const void* s) {
    asm volatile("cp.async.cg.shared.global [%0], [%1], 16;\n" :: "r"(d), "l"(s));
}
__device__ __forceinline__ void cpcommit() { asm volatile("cp.async.commit_group;\n"); }
template <int N>
__device__ __forceinline__ void cpwaitN() { asm volatile("cp.async.wait_group %0;\n" :: "n"(N)); }

__device__ __forceinline__ void ldsm4(unsigned* r, unsigned a) {
    asm volatile("ldmatrix.sync.aligned.m8n8.x4.shared.b16 {%0,%1,%2,%3}, [%4];\n"
                 : "=r"(r[0]), "=r"(r[1]), "=r"(r[2]), "=r"(r[3]) : "r"(a));
}
__device__ __forceinline__ void ldsm4t(unsigned* r, unsigned a) {
    asm volatile("ldmatrix.sync.aligned.m8n8.x4.trans.shared.b16 {%0,%1,%2,%3}, [%4];\n"
                 : "=r"(r[0]), "=r"(r[1]), "=r"(r[2]), "=r"(r[3]) : "r"(a));
}
__device__ __forceinline__ void mma16816(float* c, const unsigned* a, const unsigned* b) {
    asm volatile("mma.sync.aligned.m16n8k16.row.col.f32.f16.f16.f32 "
                 "{%0,%1,%2,%3}, {%4,%5,%6,%7}, {%8,%9}, {%0,%1,%2,%3};\n"
                 : "+f"(c[0]), "+f"(c[1]), "+f"(c[2]), "+f"(c[3])
                 : "r"(a[0]), "r"(a[1]), "r"(a[2]), "r"(a[3]), "r"(b[0]), "r"(b[1]));
}
__device__ __forceinline__ float sigm(float v) { return 1.f / (1.f + __expf(-v)); }
// fast tanh via __expf: correct limits at +/-inf, rel err ~1e-6
__device__ __forceinline__ float tanhfast(float x) {
    return 1.f - 2.f / (__expf(2.f * x) + 1.f);
}

__device__ __forceinline__ unsigned bar_acquire_ld() {
    unsigned v;
    asm volatile("ld.acquire.gpu.global.u32 %0, [%1];" : "=r"(v) : "l"(&g_bar));
    return v;
}

// ---------------- prep: state transposes + counter reset ----------------
__global__ void prep(const float* __restrict__ x, const float* __restrict__ h0) {
    long tid0 = (long)blockIdx.x * blockDim.x + threadIdx.x;
    long stride = (long)gridDim.x * blockDim.x;
    if (tid0 == 0) g_bar = 0u;
    for (long i = tid0; i < H_ * B_; i += stride) {
        int k = (int)(i >> 5), b = (int)(i & 31);
        g_xin[0][k][b] = __float2half(x[b * H_ + k]);
    }
    for (long i = tid0; i < (long)L_ * H_ * B_; i += stride) {
        int b = (int)(i & 31), k = (int)((i >> 5) & 1023), l = (int)(i >> 15);
        g_hst[0][l][k][b] = __float2half(h0[(l * B_ + b) * H_ + k]);
    }
}

// ---------------- persistent LSTM kernel ----------------
__global__ void __launch_bounds__(NTHREADS, 1)
lstm_kernel(const float* __restrict__ c0, const float* __restrict__ h0,
            const float* __restrict__ h_mask, const float* __restrict__ c_mask,
            const float* __restrict__ labels,
            const float* __restrict__ W_ih, const float* __restrict__ W_hh,
            const float* __restrict__ b_ih, const float* __restrict__ b_hh,
            float* __restrict__ out, int write_loss) {
    const int m = blockIdx.x, tid = threadIdx.x;
    const int w = tid >> 5, lane = tid & 31;

    extern __shared__ char sm_[];
    float* cst  = (float*)(sm_ + SM_C);
    float* hst  = (float*)(sm_ + SM_H);
    float* red  = (float*)(sm_ + SM_R);
    char*  W1w  = sm_ + SM_W1 + w * 16384;     // warp-private resident layer-1 W
    char*  W0w  = sm_ + SM_W0 + w * 4096;      // l0 chunks 12..15 (SMEM overflow of RF)
    char*  STGw = sm_ + SM_STG + w * WSTG;     // warp-private X staging (+partials alias)

    // exact fp32 state init for this CTA's 8 units, both layers
    for (int i = tid; i < 2 * 8 * 32; i += NTHREADS) {
        int l = i >> 8, u = (i >> 5) & 7, b = i & 31;
        int guu = m * 8 + u;
        cst[i] = c0[(l * B_ + b) * H_ + guu];
        hst[i] = h0[(l * B_ + b) * H_ + guu];
    }

    // bias regs for thread's unit (u = w): br[l][gate]
    float br[2][4];
#pragma unroll
    for (int l = 0; l < 2; l++)
#pragma unroll
        for (int g = 0; g < 4; g++) {
            int idx = l * 4096 + g * 1024 + m * 8 + w;
            br[l][g] = b_ih[idx] + b_hh[idx];
        }

    const int k0 = w * KW;
    const int aRow = lane & 15, aCol = (lane >> 4) * 8;
    const int aSel16 = ((lane >> 4) ^ ((aRow >> 2) & 1)) * 16;
    const unsigned w1su  = su(W1w);
    const unsigned w0su  = su(W0w);
    const unsigned stgsu = su(STGw);

    // ---- weight convert fp32->fp16 into swizzled SMEM chunks ----
    // chunk s (1024B, 32 rows): row i at byte i*32 + (hf ^ ((i>>2)&1))*16
    unsigned aW0[12][4], aW1[12][4];   // layer-0 A fragments, chunks 0..11 (RF)
    {
        const int kb = (w & 3) * 256;
        const int s_ = lane >> 1, hf = lane & 1;
        const float* base = (w < 4) ? W_ih : W_hh;
#pragma unroll 1
        for (int l = 0; l < 2; l++) {
            const float* Wsrc = base + (long)l * 4096 * 1024;
#pragma unroll
            for (int i = 0; i < 32; i++) {
                int srow = (i >> 3) * 1024 + m * 8 + (i & 7);
                const float* src = Wsrc + (long)srow * 1024 + kb + s_ * 16 + hf * 8;
                float4 f0 = ((const float4*)src)[0];
                float4 f1 = ((const float4*)src)[1];
                __half2 p0 = __floats2half2_rn(f0.x, f0.y);
                __half2 p1 = __floats2half2_rn(f0.z, f0.w);
                __half2 p2 = __floats2half2_rn(f1.x, f1.y);
                __half2 p3 = __floats2half2_rn(f1.z, f1.w);
                uint4 u;
                u.x = *reinterpret_cast<unsigned*>(&p0);
                u.y = *reinterpret_cast<unsigned*>(&p1);
                u.z = *reinterpret_cast<unsigned*>(&p2);
                u.w = *reinterpret_cast<unsigned*>(&p3);
                *reinterpret_cast<uint4*>(
                    W1w + s_ * 1024 + i * 32 + (hf ^ ((i >> 2) & 1)) * 16) = u;
            }
            __syncwarp();
            if (l == 0) {
                // chunks 0..11 -> RF fragments
#pragma unroll
                for (int s = 0; s < 12; s++) {
                    unsigned aB = w1su + s * 1024 + aRow * 32 + aSel16;
                    ldsm4(aW0[s], aB);
                    ldsm4(aW1[s], aB + 512);
                }
                __syncwarp();
                // chunks 12..15 -> warp-private SMEM keep-region
#pragma unroll
                for (int q = 0; q < 8; q++)
                    ((uint4*)W0w)[lane + 32 * q] =
                        ((const uint4*)(W1w + 12288))[lane + 32 * q];
                __syncwarp();
            }
        }
    }
    __syncthreads();

    float lossacc = 0.f;

    for (int n = 0; n < T_ * L_; n++) {
        const int t = n >> 1, l = n & 1;
        const bool xside = (w < 4);

        // mask/label prefetch first (independent of flag; overlaps the poll)
        const int gu = m * 8 + w;
        const long mo = ((long)(n * B_ + lane)) * H_ + gu;
        const float hmv = __ldg(h_mask + mo);
        const float cmv = __ldg(c_mask + mo);
        float labv = 0.f;
        long ro = 0;
        if (l == 1) {
            ro = ((long)(lane * T_ + t)) * H_ + gu;
            labv = __ldg(labels + ro);
        }

        // ---- dependency-aware wait: ONLY x-side warps wait for flag(n-1).
        // All lanes poll convergently (single broadcast txn; acquire per lane).
        if (xside && n) {
            const unsigned need = (unsigned)n * NCTA;
            unsigned v;
            do { v = bar_acquire_ld(); } while (v < need);
        }

        const __half* xsrc = xside ? &g_xin[n & 1][k0][0]
                                   : &g_hst[t & 1][l][k0 - 1024][0];

        // X prologue: stages 0..D-2
#pragma unroll
        for (int st = 0; st < D_ - 1; st++) {
#pragma unroll
            for (int j = 0; j < 2; j++) {
                int e = lane + 32 * j, r = e >> 2, sg = e & 3;
                cp16(stgsu + st * 1280 + r * 80 + sg * 16,
                     xsrc + (st * 16 + r) * 32 + sg * 8);
            }
            cpcommit();
        }

        float acc0[4][4], acc1[4][4];
#pragma unroll
        for (int j = 0; j < 4; j++)
#pragma unroll
            for (int q = 0; q < 4; q++) { acc0[j][q] = 0.f; acc1[j][q] = 0.f; }

        if (l == 0) {
            // A: chunks 0..11 from RF, 12..15 from SMEM keep-region
#pragma unroll
            for (int s = 0; s < 16; s++) {
                const int sp = s + D_ - 1;
                if (sp < 16) {
                    const int p2 = sp % D_;
#pragma unroll
                    for (int j = 0; j < 2; j++) {
                        int e = lane + 32 * j, r = e >> 2, sg = e & 3;
                        cp16(stgsu + p2 * 1280 + r * 80 + sg * 16,
                             xsrc + (sp * 16 + r) * 32 + sg * 8);
                    }
                }
                unsigned af0[4], af1[4];
                if (s >= 12) {
                    unsigned aB = w0su + (s - 12) * 1024 + aRow * 32 + aSel16;
                    ldsm4(af0, aB);
                    ldsm4(af1, aB + 512);
                }
                cpcommit();
                cpwaitN<D_ - 1>();
                __syncwarp();
                const int p = s % D_;
                unsigned b0[4], b1[4];
                unsigned xB = stgsu + p * 1280 + aRow * 80 + aCol * 2;
                ldsm4t(b0, xB);
                ldsm4t(b1, xB + 32);
                if (s < 12) {
                    mma16816(acc0[0], aW0[s], b0 + 0); mma16816(acc0[1], aW0[s], b0 + 2);
                    mma16816(acc0[2], aW0[s], b1 + 0); mma16816(acc0[3], aW0[s], b1 + 2);
                    mma16816(acc1[0], aW1[s], b0 + 0); mma16816(acc1[1], aW1[s], b0 + 2);
                    mma16816(acc1[2], aW1[s], b1 + 0); mma16816(acc1[3], aW1[s], b1 + 2);
                } else {
                    mma16816(acc0[0], af0, b0 + 0); mma16816(acc0[1], af0, b0 + 2);
                    mma16816(acc0[2], af0, b1 + 0); mma16816(acc0[3], af0, b1 + 2);
                    mma16816(acc1[0], af1, b0 + 0); mma16816(acc1[1], af1, b0 + 2);
                    mma16816(acc1[2], af1, b1 + 0); mma16816(acc1[3], af1, b1 + 2);
                }
            }
        } else {
            // A from resident SMEM (layer 1)
#pragma unroll
            for (int s = 0; s < 16; s++) {
                const int sp = s + D_ - 1;
                if (sp < 16) {
                    const int p2 = sp % D_;
#pragma unroll
                    for (int j = 0; j < 2; j++) {
                        int e = lane + 32 * j, r = e >> 2, sg = e & 3;
                        cp16(stgsu + p2 * 1280 + r * 80 + sg * 16,
                             xsrc + (sp * 16 + r) * 32 + sg * 8);
                    }
                }
                unsigned a0[4], a1[4];
                unsigned aB = w1su + s * 1024 + aRow * 32 + aSel16;
                ldsm4(a0, aB);
                ldsm4(a1, aB + 512);
                cpcommit();
                cpwaitN<D_ - 1>();
                __syncwarp();
                const int p = s % D_;
                unsigned b0[4], b1[4];
                unsigned xB = stgsu + p * 1280 + aRow * 80 + aCol * 2;
                ldsm4t(b0, xB);
                ldsm4t(b1, xB + 32);
                mma16816(acc0[0], a0, b0 + 0); mma16816(acc0[1], a0, b0 + 2);
                mma16816(acc0[2], a0, b1 + 0); mma16816(acc0[3], a0, b1 + 2);
                mma16816(acc1[0], a1, b0 + 0); mma16816(acc1[1], a1, b0 + 2);
                mma16816(acc1[2], a1, b1 + 0); mma16816(acc1[3], a1, b1 + 2);
            }
        }

        // ---- partials: WARP-LOCAL region (aliases own staging; no pre-sync) ----
        {
            float* pw = (float*)STGw;
#pragma unroll
            for (int f = 0; f < 2; f++) {
                float (*ac)[4] = f ? acc1 : acc0;
#pragma unroll
                for (int j = 0; j < 4; j++) {
                    int r0 = f * 16 + (lane >> 2), col = j * 8 + (lane & 3) * 2;
                    pw[r0 * 33 + col]           = ac[j][0];
                    pw[r0 * 33 + col + 1]       = ac[j][1];
                    pw[(r0 + 8) * 33 + col]     = ac[j][2];
                    pw[(r0 + 8) * 33 + col + 1] = ac[j][3];
                }
            }
        }
        __syncthreads();

        // ---- cell math: thread (u=w, b=lane) ----
        {
            float g[4];
#pragma unroll
            for (int gg = 0; gg < 4; gg++) {
                float ssum = 0.f;
#pragma unroll
                for (int ww = 0; ww < 8; ww++)
                    ssum += ((float*)(sm_ + SM_STG + ww * WSTG))[(gg * 8 + w) * 33 + lane];
                g[gg] = ssum + br[l][gg];
            }
            const int si = (l * 8 + w) * 32 + lane;
            float cold = cst[si], hold = hst[si];
            float ccand = sigm(g[1]) * cold + sigm(g[0]) * tanhfast(g[2]);
            float hcand = sigm(g[3]) * tanhfast(ccand);
            float cn = cmv * cold + (1.f - cmv) * ccand;
            float hn = hmv * hold + (1.f - hmv) * hcand;
            cst[si] = cn;
            hst[si] = hn;
            __half hh = __float2half(hn);
            g_xin[(n + 1) & 1][gu][lane] = hh;
            g_hst[(t & 1) ^ 1][l][gu][lane] = hh;
            if (l == 1) {
                out[ro] = hn;
                float d = hn - labv;
                lossacc += d * d;
            }
        }
        __syncthreads();            // partial reads + h stores complete CTA-wide
        if (tid == 0)
            asm volatile("red.release.gpu.global.add.u32 [%0], %1;\n"
                         :: "l"(&g_bar), "r"(1u));
        // h-side warps of cell n+1 proceed immediately; x-side warps poll next.
    }

    // ---- deterministic loss reduction ----
    red[tid] = lossacc;
    __syncthreads();
    for (int sft = 128; sft > 0; sft >>= 1) {
        if (tid < sft) red[tid] += red[tid + sft];
        __syncthreads();
    }
    if (tid == 0) {
        g_losspart[m] = red[0];
        asm volatile("red.release.gpu.global.add.u32 [%0], %1;\n"
                     :: "l"(&g_bar), "r"(1u));
        if (m == 0 && write_loss) {
            const unsigned need = (unsigned)(T_ * L_ + 1) * NCTA;
            unsigned v;
            do { v = bar_acquire_ld(); } while (v < need);
            float ssum = 0.f;
            for (int i = 0; i < NCTA; i++) ssum += g_losspart[i];
            out[RET_ELEMS] = ssum / (float)RET_ELEMS;
        }
    }
}

// ---------------- launch ----------------
extern "C" void kernel_launch(void* const* d_in, const int* in_sizes, int n_in,
                              void* d_out, int out_size) {
    const float* x      = (const float*)d_in[0];
    const float* h0     = (const float*)d_in[1];
    const float* c0     = (const float*)d_in[2];
    const float* h_mask = (const float*)d_in[3];
    const float* c_mask = (const float*)d_in[4];
    const float* labels = (const float*)d_in[5];
    const float* W_ih   = (const float*)d_in[6];
    const float* W_hh   = (const float*)d_in[7];
    const float* b_ih   = (const float*)d_in[8];
    const float* b_hh   = (const float*)d_in[9];
    float* out = (float*)d_out;

    cudaFuncSetAttribute(lstm_kernel, cudaFuncAttributeMaxDynamicSharedMemorySize,
                         SMEM_TOTAL);

    prep<<<128, 256>>>(x, h0);
    int write_loss = (out_size > RET_ELEMS) ? 1 : 0;
    lstm_kernel<<<NCTA, NTHREADS, SMEM_TOTAL>>>(c0, h0, h_mask, c_mask, labels,
                                                W_ih, W_hh, b_ih, b_hh, out,
                                                write_loss);
}

// round 16
// speedup vs baseline: 1.1057x; 1.0054x over previous
#include <cuda_runtime.h>
#include <cuda_fp16.h>
#include <math.h>

// ---------------- problem constants ----------------
#define L_    2
#define B_    32
#define T_    16
#define H_    1024
#define K_    2048
#define NCTA  128           // 32 gate rows per CTA (8 units x 4 gates)
#define ROWS  32
#define NTHREADS 256
#define KW    256           // K slice per warp
#define D_    5             // X cp.async pipeline depth (stages of k16)
#define WSTG  6400          // per-warp staging bytes (5 * 1280); partials alias [0,4224)
#define RET_ELEMS (B_*T_*H_)

// smem layout (bytes)
#define SM_W1  0                        // 8 warps * 16KB resident layer-1 W = 131072
#define SM_STG 131072                   // 8 * 6400 = 51200 (stages; warp-local partials alias)
#define SM_W0  182272                   // 8 * 4096 = 32768 (l0 chunks 12..15 per warp)
#define SM_C   215040                   // 2048
#define SM_H   217088                   // 2048
#define SM_R   219136                   // 1024
#define SMEM_TOTAL 220160

// ---------------- device globals (scratch; no allocs) ----------------
__device__ __half  g_xin[2][H_][B_];          // chain input, parity by n
__device__ __half  g_hst[2][L_][H_][B_];      // per-layer h state, parity by t
__device__ float   g_losspart[NCTA];
__device__ unsigned g_bar;

// ---------------- helpers ----------------
__device__ __forceinline__ unsigned su(const void* p) {
    return (unsigned)__cvta_generic_to_shared(p);
}
__device__ __forceinline__ void cp16(unsigned d, const void* s) {
    asm volatile("cp.async.cg.shared.global [%0], [%1], 16;\n" :: "r"(d), "l"(s));
}
__device__ __forceinline__ void cpcommit() { asm volatile("cp.async.commit_group;\n"); }
template <int N>
__device__ __forceinline__ void cpwaitN() { asm volatile("cp.async.wait_group %0;\n" :: "n"(N)); }

__device__ __forceinline__ void ldsm4(unsigned* r, unsigned a) {
    asm volatile("ldmatrix.sync.aligned.m8n8.x4.shared.b16 {%0,%1,%2,%3}, [%4];\n"
                 : "=r"(r[0]), "=r"(r[1]), "=r"(r[2]), "=r"(r[3]) : "r"(a));
}
__device__ __forceinline__ void ldsm4t(unsigned* r, unsigned a) {
    asm volatile("ldmatrix.sync.aligned.m8n8.x4.trans.shared.b16 {%0,%1,%2,%3}, [%4];\n"
                 : "=r"(r[0]), "=r"(r[1]), "=r"(r[2]), "=r"(r[3]) : "r"(a));
}
__device__ __forceinline__ void mma16816(float* c, const unsigned* a, const unsigned* b) {
    asm volatile("mma.sync.aligned.m16n8k16.row.col.f32.f16.f16.f32 "
                 "{%0,%1,%2,%3}, {%4,%5,%6,%7}, {%8,%9}, {%0,%1,%2,%3};\n"
                 : "+f"(c[0]), "+f"(c[1]), "+f"(c[2]), "+f"(c[3])
                 : "r"(a[0]), "r"(a[1]), "r"(a[2]), "r"(a[3]), "r"(b[0]), "r"(b[1]));
}
__device__ __forceinline__ float sigm(float v) { return 1.f / (1.f + __expf(-v)); }
// fast tanh via __expf: correct limits at +/-inf, rel err ~1e-6
__device__ __forceinline__ float tanhfast(float x) {
    return 1.f - 2.f / (__expf(2.f * x) + 1.f);
}

__device__ __forceinline__ unsigned bar_acquire_ld() {
    unsigned v;
    asm volatile("ld.acquire.gpu.global.u32 %0, [%1];" : "=r"(v) : "l"(&g_bar));
    return v;
}

// ---------------- prep: state transposes + counter reset ----------------
__global__ void prep(const float* __restrict__ x, const float* __restrict__ h0) {
    long tid0 = (long)blockIdx.x * blockDim.x + threadIdx.x;
    long stride = (long)gridDim.x * blockDim.x;
    if (tid0 == 0) g_bar = 0u;
    for (long i = tid0; i < H_ * B_; i += stride) {
        int k = (int)(i >> 5), b = (int)(i & 31);
        g_xin[0][k][b] = __float2half(x[b * H_ + k]);
    }
    for (long i = tid0; i < (long)L_ * H_ * B_; i += stride) {
        int b = (int)(i & 31), k = (int)((i >> 5) & 1023), l = (int)(i >> 15);
        g_hst[0][l][k][b] = __float2half(h0[(l * B_ + b) * H_ + k]);
    }
}

// ---------------- persistent LSTM kernel ----------------
__global__ void __launch_bounds__(NTHREADS, 1)
lstm_kernel(const float* __restrict__ c0, const float* __restrict__ h0,
            const float* __restrict__ h_mask, const float* __restrict__ c_mask,
            const float* __restrict__ labels,
            const float* __restrict__ W_ih, const float* __restrict__ W_hh,
            const float* __restrict__ b_ih, const float* __restrict__ b_hh,
            float* __restrict__ out, int write_loss) {
    const int m = blockIdx.x, tid = threadIdx.x;
    const int w = tid >> 5, lane = tid & 31;

    extern __shared__ char sm_[];
    float* cst  = (float*)(sm_ + SM_C);
    float* hst  = (float*)(sm_ + SM_H);
    float* red  = (float*)(sm_ + SM_R);
    char*  W1w  = sm_ + SM_W1 + w * 16384;     // warp-private resident layer-1 W
    char*  W0w  = sm_ + SM_W0 + w * 4096;      // l0 chunks 12..15 (SMEM overflow of RF)
    char*  STGw = sm_ + SM_STG + w * WSTG;     // warp-private X staging (+partials alias)

    // exact fp32 state init for this CTA's 8 units, both layers
    for (int i = tid; i < 2 * 8 * 32; i += NTHREADS) {
        int l = i >> 8, u = (i >> 5) & 7, b = i & 31;
        int guu = m * 8 + u;
        cst[i] = c0[(l * B_ + b) * H_ + guu];
        hst[i] = h0[(l * B_ + b) * H_ + guu];
    }

    // bias regs for thread's unit (u = w): br[l][gate]
    float br[2][4];
#pragma unroll
    for (int l = 0; l < 2; l++)
#pragma unroll
        for (int g = 0; g < 4; g++) {
            int idx = l * 4096 + g * 1024 + m * 8 + w;
            br[l][g] = b_ih[idx] + b_hh[idx];
        }

    const int k0 = w * KW;
    const int aRow = lane & 15, aCol = (lane >> 4) * 8;
    const int aSel16 = ((lane >> 4) ^ ((aRow >> 2) & 1)) * 16;
    const unsigned w1su  = su(W1w);
    const unsigned w0su  = su(W0w);
    const unsigned stgsu = su(STGw);

    // ---- weight convert fp32->fp16 into swizzled SMEM chunks ----
    // chunk s (1024B, 32 rows): row i at byte i*32 + (hf ^ ((i>>2)&1))*16
    unsigned aW0[12][4], aW1[12][4];   // layer-0 A fragments, chunks 0..11 (RF)
    {
        const int kb = (w & 3) * 256;
        const int s_ = lane >> 1, hf = lane & 1;
        const float* base = (w < 4) ? W_ih : W_hh;
#pragma unroll 1
        for (int l = 0; l < 2; l++) {
            const float* Wsrc = base + (long)l * 4096 * 1024;
#pragma unroll
            for (int i = 0; i < 32; i++) {
                int srow = (i >> 3) * 1024 + m * 8 + (i & 7);
                const float* src = Wsrc + (long)srow * 1024 + kb + s_ * 16 + hf * 8;
                float4 f0 = ((const float4*)src)[0];
                float4 f1 = ((const float4*)src)[1];
                __half2 p0 = __floats2half2_rn(f0.x, f0.y);
                __half2 p1 = __floats2half2_rn(f0.z, f0.w);
                __half2 p2 = __floats2half2_rn(f1.x, f1.y);
                __half2 p3 = __floats2half2_rn(f1.z, f1.w);
                uint4 u;
                u.x = *reinterpret_cast<unsigned*>(&p0);
                u.y = *reinterpret_cast<unsigned*>(&p1);
                u.z = *reinterpret_cast<unsigned*>(&p2);
                u.w = *reinterpret_cast<unsigned*>(&p3);
                *reinterpret_cast<uint4*>(
                    W1w + s_ * 1024 + i * 32 + (hf ^ ((i >> 2) & 1)) * 16) = u;
            }
            __syncwarp();
            if (l == 0) {
                // chunks 0..11 -> RF fragments
#pragma unroll
                for (int s = 0; s < 12; s++) {
                    unsigned aB = w1su + s * 1024 + aRow * 32 + aSel16;
                    ldsm4(aW0[s], aB);
                    ldsm4(aW1[s], aB + 512);
                }
                __syncwarp();
                // chunks 12..15 -> warp-private SMEM keep-region
#pragma unroll
                for (int q = 0; q < 8; q++)
                    ((uint4*)W0w)[lane + 32 * q] =
                        ((const uint4*)(W1w + 12288))[lane + 32 * q];
                __syncwarp();
            }
        }
    }
    __syncthreads();

    float lossacc = 0.f;

    for (int n = 0; n < T_ * L_; n++) {
        const int t = n >> 1, l = n & 1;
        const bool xside = (w < 4);

        // mask/label prefetch first (independent of flag; overlaps the poll)
        const int gu = m * 8 + w;
        const long mo = ((long)(n * B_ + lane)) * H_ + gu;
        const float hmv = __ldg(h_mask + mo);
        const float cmv = __ldg(c_mask + mo);
        float labv = 0.f;
        long ro = 0;
        if (l == 1) {
            ro = ((long)(lane * T_ + t)) * H_ + gu;
            labv = __ldg(labels + ro);
        }

        // ---- dependency-aware wait: only warp 0 polls (1 L2 access/CTA/round);
        // x-warps rendezvous on a named barrier. Release+acquire+barrier edges
        // order the subsequent cp.async.cg L2 reads (L1 bypassed).
        if (xside && n) {
            if (w == 0) {
                const unsigned need = (unsigned)n * NCTA;
                if (lane == 0) {
                    unsigned v;
                    do { v = bar_acquire_ld(); } while (v < need);
                }
                __syncwarp();
            }
            asm volatile("bar.sync 1, 128;" ::: "memory");
        }

        const __half* xsrc = xside ? &g_xin[n & 1][k0][0]
                                   : &g_hst[t & 1][l][k0 - 1024][0];

        // X prologue: stages 0..D-2
#pragma unroll
        for (int st = 0; st < D_ - 1; st++) {
#pragma unroll
            for (int j = 0; j < 2; j++) {
                int e = lane + 32 * j, r = e >> 2, sg = e & 3;
                cp16(stgsu + st * 1280 + r * 80 + sg * 16,
                     xsrc + (st * 16 + r) * 32 + sg * 8);
            }
            cpcommit();
        }

        float acc0[4][4], acc1[4][4];
#pragma unroll
        for (int j = 0; j < 4; j++)
#pragma unroll
            for (int q = 0; q < 4; q++) { acc0[j][q] = 0.f; acc1[j][q] = 0.f; }

        if (l == 0) {
            // A: chunks 0..11 from RF, 12..15 from SMEM keep-region
#pragma unroll
            for (int s = 0; s < 16; s++) {
                const int sp = s + D_ - 1;
                if (sp < 16) {
                    const int p2 = sp % D_;
#pragma unroll
                    for (int j = 0; j < 2; j++) {
                        int e = lane + 32 * j, r = e >> 2, sg = e & 3;
                        cp16(stgsu + p2 * 1280 + r * 80 + sg * 16,
                             xsrc + (sp * 16 + r) * 32 + sg * 8);
                    }
                }
                unsigned af0[4], af1[4];
                if (s >= 12) {
                    unsigned aB = w0su + (s - 12) * 1024 + aRow * 32 + aSel16;
                    ldsm4(af0, aB);
                    ldsm4(af1, aB + 512);
                }
                cpcommit();
                cpwaitN<D_ - 1>();
                __syncwarp();
                const int p = s % D_;
                unsigned b0[4], b1[4];
                unsigned xB = stgsu + p * 1280 + aRow * 80 + aCol * 2;
                ldsm4t(b0, xB);
                ldsm4t(b1, xB + 32);
                if (s < 12) {
                    mma16816(acc0[0], aW0[s], b0 + 0); mma16816(acc0[1], aW0[s], b0 + 2);
                    mma16816(acc0[2], aW0[s], b1 + 0); mma16816(acc0[3], aW0[s], b1 + 2);
                    mma16816(acc1[0], aW1[s], b0 + 0); mma16816(acc1[1], aW1[s], b0 + 2);
                    mma16816(acc1[2], aW1[s], b1 + 0); mma16816(acc1[3], aW1[s], b1 + 2);
                } else {
                    mma16816(acc0[0], af0, b0 + 0); mma16816(acc0[1], af0, b0 + 2);
                    mma16816(acc0[2], af0, b1 + 0); mma16816(acc0[3], af0, b1 + 2);
                    mma16816(acc1[0], af1, b0 + 0); mma16816(acc1[1], af1, b0 + 2);
                    mma16816(acc1[2], af1, b1 + 0); mma16816(acc1[3], af1, b1 + 2);
                }
            }
        } else {
            // A from resident SMEM (layer 1)
#pragma unroll
            for (int s = 0; s < 16; s++) {
                const int sp = s + D_ - 1;
                if (sp < 16) {
                    const int p2 = sp % D_;
#pragma unroll
                    for (int j = 0; j < 2; j++) {
                        int e = lane + 32 * j, r = e >> 2, sg = e & 3;
                        cp16(stgsu + p2 * 1280 + r * 80 + sg * 16,
                             xsrc + (sp * 16 + r) * 32 + sg * 8);
                    }
                }
                unsigned a0[4], a1[4];
                unsigned aB = w1su + s * 1024 + aRow * 32 + aSel16;
                ldsm4(a0, aB);
                ldsm4(a1, aB + 512);
                cpcommit();
                cpwaitN<D_ - 1>();
                __syncwarp();
                const int p = s % D_;
                unsigned b0[4], b1[4];
                unsigned xB = stgsu + p * 1280 + aRow * 80 + aCol * 2;
                ldsm4t(b0, xB);
                ldsm4t(b1, xB + 32);
                mma16816(acc0[0], a0, b0 + 0); mma16816(acc0[1], a0, b0 + 2);
                mma16816(acc0[2], a0, b1 + 0); mma16816(acc0[3], a0, b1 + 2);
                mma16816(acc1[0], a1, b0 + 0); mma16816(acc1[1], a1, b0 + 2);
                mma16816(acc1[2], a1, b1 + 0); mma16816(acc1[3], a1, b1 + 2);
            }
        }

        // ---- partials: WARP-LOCAL region (aliases own staging; no pre-sync) ----
        {
            float* pw = (float*)STGw;
#pragma unroll
            for (int f = 0; f < 2; f++) {
                float (*ac)[4] = f ? acc1 : acc0;
#pragma unroll
                for (int j = 0; j < 4; j++) {
                    int r0 = f * 16 + (lane >> 2), col = j * 8 + (lane & 3) * 2;
                    pw[r0 * 33 + col]           = ac[j][0];
                    pw[r0 * 33 + col + 1]       = ac[j][1];
                    pw[(r0 + 8) * 33 + col]     = ac[j][2];
                    pw[(r0 + 8) * 33 + col + 1] = ac[j][3];
                }
            }
        }
        __syncthreads();

        // ---- cell math: thread (u=w, b=lane) ----
        {
            float g[4];
#pragma unroll
            for (int gg = 0; gg < 4; gg++) {
                float ssum = 0.f;
#pragma unroll
                for (int ww = 0; ww < 8; ww++)
                    ssum += ((float*)(sm_ + SM_STG + ww * WSTG))[(gg * 8 + w) * 33 + lane];
                g[gg] = ssum + br[l][gg];
            }
            const int si = (l * 8 + w) * 32 + lane;
            float cold = cst[si], hold = hst[si];
            float ccand = sigm(g[1]) * cold + sigm(g[0]) * tanhfast(g[2]);
            float hcand = sigm(g[3]) * tanhfast(ccand);
            float cn = cmv * cold + (1.f - cmv) * ccand;
            float hn = hmv * hold + (1.f - hmv) * hcand;
            cst[si] = cn;
            hst[si] = hn;
            __half hh = __float2half(hn);
            g_xin[(n + 1) & 1][gu][lane] = hh;
            g_hst[(t & 1) ^ 1][l][gu][lane] = hh;
            if (l == 1) {
                out[ro] = hn;
                float d = hn - labv;
                lossacc += d * d;
            }
        }
        __syncthreads();            // partial reads + h stores complete CTA-wide
        if (tid == 0)
            asm volatile("red.release.gpu.global.add.u32 [%0], %1;\n"
                         :: "l"(&g_bar), "r"(1u));
        // h-side warps of cell n+1 proceed immediately; x-side warps poll next.
    }

    // ---- deterministic loss reduction ----
    red[tid] = lossacc;
    __syncthreads();
    for (int sft = 128; sft > 0; sft >>= 1) {
        if (tid < sft) red[tid] += red[tid + sft];
        __syncthreads();
    }
    if (tid == 0) {
        g_losspart[m] = red[0];
        asm volatile("red.release.gpu.global.add.u32 [%0], %1;\n"
                     :: "l"(&g_bar), "r"(1u));
        if (m == 0 && write_loss) {
            const unsigned need = (unsigned)(T_ * L_ + 1) * NCTA;
            unsigned v;
            do { v = bar_acquire_ld(); } while (v < need);
            float ssum = 0.f;
            for (int i = 0; i < NCTA; i++) ssum += g_losspart[i];
            out[RET_ELEMS] = ssum / (float)RET_ELEMS;
        }
    }
}

// ---------------- launch ----------------
extern "C" void kernel_launch(void* const* d_in, const int* in_sizes, int n_in,
                              void* d_out, int out_size) {
    const float* x      = (const float*)d_in[0];
    const float* h0     = (const float*)d_in[1];
    const float* c0     = (const float*)d_in[2];
    const float* h_mask = (const float*)d_in[3];
    const float* c_mask = (const float*)d_in[4];
    const float* labels = (const float*)d_in[5];
    const float* W_ih   = (const float*)d_in[6];
    const float* W_hh   = (const float*)d_in[7];
    const float* b_ih   = (const float*)d_in[8];
    const float* b_hh   = (const float*)d_in[9];
    float* out = (float*)d_out;

    cudaFuncSetAttribute(lstm_kernel, cudaFuncAttributeMaxDynamicSharedMemorySize,
                         SMEM_TOTAL);

    prep<<<128, 256>>>(x, h0);
    int write_loss = (out_size > RET_ELEMS) ? 1 : 0;
    lstm_kernel<<<NCTA, NTHREADS, SMEM_TOTAL>>>(c0, h0, h_mask, c_mask, labels,
                                                W_ih, W_hh, b_ih, b_hh, out,
                                                write_loss);
}

// round 17
// speedup vs baseline: 1.2233x; 1.1064x over previous
#include <cuda_runtime.h>
#include <cuda_fp16.h>
#include <math.h>

// ---------------- problem constants ----------------
#define L_    2
#define B_    32
#define T_    16
#define H_    1024
#define K_    2048
#define NCTA  128           // 32 gate rows per CTA (8 units x 4 gates)
#define ROWS  32
#define NTHREADS 256
#define KW    256           // K slice per warp
#define D_    5             // l0 pipeline depth (static)
#define D1    4             // l1 pipeline depth (dynamic rot; power-of-2 masks)
#define WSTG  6400          // per-warp staging bytes (5 * 1280); partials alias [0,4224)
#define RET_ELEMS (B_*T_*H_)

// smem layout (bytes)
#define SM_W1  0                        // 8 warps * 16KB resident layer-1 W = 131072
#define SM_STG 131072                   // 8 * 6400 = 51200 (stages; warp-local partials alias)
#define SM_W0  182272                   // 8 * 4096 = 32768 (l0 chunks 12..15 per warp)
#define SM_C   215040                   // 2048
#define SM_H   217088                   // 2048
#define SM_R   219136                   // 1024
#define SMEM_TOTAL 220160

// ---------------- device globals (scratch; no allocs) ----------------
__device__ __half  g_xin[2][H_][B_];          // chain input, parity by n
__device__ __half  g_hst[2][L_][H_][B_];      // per-layer h state, parity by t
__device__ float   g_losspart[NCTA];
__device__ unsigned g_bar;

// ---------------- helpers ----------------
__device__ __forceinline__ unsigned su(const void* p) {
    return (unsigned)__cvta_generic_to_shared(p);
}
__device__ __forceinline__ void cp16(unsigned d, const void* s) {
    asm volatile("cp.async.cg.shared.global [%0], [%1], 16;\n" :: "r"(d), "l"(s));
}
__device__ __forceinline__ void cpcommit() { asm volatile("cp.async.commit_group;\n"); }
template <int N>
__device__ __forceinline__ void cpwaitN() { asm volatile("cp.async.wait_group %0;\n" :: "n"(N)); }

__device__ __forceinline__ void ldsm4(unsigned* r, unsigned a) {
    asm volatile("ldmatrix.sync.aligned.m8n8.x4.shared.b16 {%0,%1,%2,%3}, [%4];\n"
                 : "=r"(r[0]), "=r"(r[1]), "=r"(r[2]), "=r"(r[3]) : "r"(a));
}
__device__ __forceinline__ void ldsm4t(unsigned* r, unsigned a) {
    asm volatile("ldmatrix.sync.aligned.m8n8.x4.trans.shared.b16 {%0,%1,%2,%3}, [%4];\n"
                 : "=r"(r[0]), "=r"(r[1]), "=r"(r[2]), "=r"(r[3]) : "r"(a));
}
__device__ __forceinline__ void mma16816(float* c, const unsigned* a, const unsigned* b) {
    asm volatile("mma.sync.aligned.m16n8k16.row.col.f32.f16.f16.f32 "
                 "{%0,%1,%2,%3}, {%4,%5,%6,%7}, {%8,%9}, {%0,%1,%2,%3};\n"
                 : "+f"(c[0]), "+f"(c[1]), "+f"(c[2]), "+f"(c[3])
                 : "r"(a[0]), "r"(a[1]), "r"(a[2]), "r"(a[3]), "r"(b[0]), "r"(b[1]));
}
__device__ __forceinline__ float sigm(float v) { return 1.f / (1.f + __expf(-v)); }
__device__ __forceinline__ float tanhfast(float x) {
    return 1.f - 2.f / (__expf(2.f * x) + 1.f);
}

__device__ __forceinline__ unsigned bar_acquire_ld() {
    unsigned v;
    asm volatile("ld.acquire.gpu.global.u32 %0, [%1];" : "=r"(v) : "l"(&g_bar));
    return v;
}

// ---- layer-0 GEMM: A chunks 0..11 from RF, 12..15 from SMEM; static rotation ----
template <int ROT>
__device__ __forceinline__ void gemm_l0(
    unsigned stgsu, unsigned w0su, const __half* __restrict__ xsrc,
    const unsigned (*aW0)[4], const unsigned (*aW1)[4],
    float (*acc0)[4], float (*acc1)[4],
    int lane, int aRow, int aCol, int aSel16)
{
#pragma unroll
    for (int st = 0; st < D_ - 1; st++) {
        const int c = (st + ROT) & 15;
#pragma unroll
        for (int j = 0; j < 2; j++) {
            int e = lane + 32 * j, r = e >> 2, sg = e & 3;
            cp16(stgsu + st * 1280 + r * 80 + sg * 16,
                 xsrc + (c * 16 + r) * 32 + sg * 8);
        }
        cpcommit();
    }
#pragma unroll
    for (int s = 0; s < 16; s++) {
        const int sp = s + D_ - 1;
        if (sp < 16) {
            const int p2 = sp % D_;
            const int pc = (sp + ROT) & 15;
#pragma unroll
            for (int j = 0; j < 2; j++) {
                int e = lane + 32 * j, r = e >> 2, sg = e & 3;
                cp16(stgsu + p2 * 1280 + r * 80 + sg * 16,
                     xsrc + (pc * 16 + r) * 32 + sg * 8);
            }
        }
        const int c = (s + ROT) & 15;
        unsigned af0[4], af1[4];
        if (c >= 12) {
            unsigned aB = w0su + (c - 12) * 1024 + aRow * 32 + aSel16;
            ldsm4(af0, aB);
            ldsm4(af1, aB + 512);
        }
        cpcommit();
        cpwaitN<D_ - 1>();
        __syncwarp();
        const int p = s % D_;
        unsigned b0[4], b1[4];
        unsigned xB = stgsu + p * 1280 + aRow * 80 + aCol * 2;
        ldsm4t(b0, xB);
        ldsm4t(b1, xB + 32);
        if (c < 12) {
            mma16816(acc0[0], aW0[c], b0 + 0); mma16816(acc0[1], aW0[c], b0 + 2);
            mma16816(acc0[2], aW0[c], b1 + 0); mma16816(acc0[3], aW0[c], b1 + 2);
            mma16816(acc1[0], aW1[c], b0 + 0); mma16816(acc1[1], aW1[c], b0 + 2);
            mma16816(acc1[2], aW1[c], b1 + 0); mma16816(acc1[3], aW1[c], b1 + 2);
        } else {
            mma16816(acc0[0], af0, b0 + 0); mma16816(acc0[1], af0, b0 + 2);
            mma16816(acc0[2], af0, b1 + 0); mma16816(acc0[3], af0, b1 + 2);
            mma16816(acc1[0], af1, b0 + 0); mma16816(acc1[1], af1, b0 + 2);
            mma16816(acc1[2], af1, b1 + 0); mma16816(acc1[3], af1, b1 + 2);
        }
    }
}

// ---- layer-1 GEMM: A fully SMEM-resident; dynamic rotation; depth D1 ----
__device__ __forceinline__ void gemm_l1(
    unsigned stgsu, unsigned w1su, const __half* __restrict__ xsrc, int rot,
    float (*acc0)[4], float (*acc1)[4],
    int lane, int aRow, int aCol, int aSel16)
{
#pragma unroll
    for (int st = 0; st < D1 - 1; st++) {
        const int c = (st + rot) & 15;
#pragma unroll
        for (int j = 0; j < 2; j++) {
            int e = lane + 32 * j, r = e >> 2, sg = e & 3;
            cp16(stgsu + st * 1280 + r * 80 + sg * 16,
                 xsrc + (c * 16 + r) * 32 + sg * 8);
        }
        cpcommit();
    }
#pragma unroll 4
    for (int s = 0; s < 16; s++) {
        const int sp = s + D1 - 1;
        if (sp < 16) {
            const int p2 = sp & (D1 - 1);
            const int pc = (sp + rot) & 15;
#pragma unroll
            for (int j = 0; j < 2; j++) {
                int e = lane + 32 * j, r = e >> 2, sg = e & 3;
                cp16(stgsu + p2 * 1280 + r * 80 + sg * 16,
                     xsrc + (pc * 16 + r) * 32 + sg * 8);
            }
        }
        const int c = (s + rot) & 15;
        unsigned a0[4], a1[4];
        unsigned aB = w1su + c * 1024 + aRow * 32 + aSel16;
        ldsm4(a0, aB);
        ldsm4(a1, aB + 512);
        cpcommit();
        cpwaitN<D1 - 1>();
        __syncwarp();
        const int p = s & (D1 - 1);
        unsigned b0[4], b1[4];
        unsigned xB = stgsu + p * 1280 + aRow * 80 + aCol * 2;
        ldsm4t(b0, xB);
        ldsm4t(b1, xB + 32);
        mma16816(acc0[0], a0, b0 + 0); mma16816(acc0[1], a0, b0 + 2);
        mma16816(acc0[2], a0, b1 + 0); mma16816(acc0[3], a0, b1 + 2);
        mma16816(acc1[0], a1, b0 + 0); mma16816(acc1[1], a1, b0 + 2);
        mma16816(acc1[2], a1, b1 + 0); mma16816(acc1[3], a1, b1 + 2);
    }
}

// ---------------- prep: state transposes + counter reset ----------------
__global__ void prep(const float* __restrict__ x, const float* __restrict__ h0) {
    long tid0 = (long)blockIdx.x * blockDim.x + threadIdx.x;
    long stride = (long)gridDim.x * blockDim.x;
    if (tid0 == 0) g_bar = 0u;
    for (long i = tid0; i < H_ * B_; i += stride) {
        int k = (int)(i >> 5), b = (int)(i & 31);
        g_xin[0][k][b] = __float2half(x[b * H_ + k]);
    }
    for (long i = tid0; i < (long)L_ * H_ * B_; i += stride) {
        int b = (int)(i & 31), k = (int)((i >> 5) & 1023), l = (int)(i >> 15);
        g_hst[0][l][k][b] = __float2half(h0[(l * B_ + b) * H_ + k]);
    }
}

// ---------------- persistent LSTM kernel ----------------
__global__ void __launch_bounds__(NTHREADS, 1)
lstm_kernel(const float* __restrict__ c0, const float* __restrict__ h0,
            const float* __restrict__ h_mask, const float* __restrict__ c_mask,
            const float* __restrict__ labels,
            const float* __restrict__ W_ih, const float* __restrict__ W_hh,
            const float* __restrict__ b_ih, const float* __restrict__ b_hh,
            float* __restrict__ out, int write_loss) {
    const int m = blockIdx.x, tid = threadIdx.x;
    const int w = tid >> 5, lane = tid & 31;

    extern __shared__ char sm_[];
    float* cst  = (float*)(sm_ + SM_C);
    float* hst  = (float*)(sm_ + SM_H);
    float* red  = (float*)(sm_ + SM_R);
    char*  W1w  = sm_ + SM_W1 + w * 16384;     // warp-private resident layer-1 W
    char*  W0w  = sm_ + SM_W0 + w * 4096;      // l0 chunks 12..15 (SMEM overflow of RF)
    char*  STGw = sm_ + SM_STG + w * WSTG;     // warp-private X staging (+partials alias)

    // exact fp32 state init for this CTA's 8 units, both layers
    for (int i = tid; i < 2 * 8 * 32; i += NTHREADS) {
        int l = i >> 8, u = (i >> 5) & 7, b = i & 31;
        int guu = m * 8 + u;
        cst[i] = c0[(l * B_ + b) * H_ + guu];
        hst[i] = h0[(l * B_ + b) * H_ + guu];
    }

    // bias regs for thread's unit (u = w): br[l][gate]
    float br[2][4];
#pragma unroll
    for (int l = 0; l < 2; l++)
#pragma unroll
        for (int g = 0; g < 4; g++) {
            int idx = l * 4096 + g * 1024 + m * 8 + w;
            br[l][g] = b_ih[idx] + b_hh[idx];
        }

    const int k0 = w * KW;
    const int aRow = lane & 15, aCol = (lane >> 4) * 8;
    const int aSel16 = ((lane >> 4) ^ ((aRow >> 2) & 1)) * 16;
    const unsigned w1su  = su(W1w);
    const unsigned w0su  = su(W0w);
    const unsigned stgsu = su(STGw);
    const int rot1 = (m * 5) & 15;             // l1 dynamic de-camping rotation

    // ---- weight convert fp32->fp16 into swizzled SMEM chunks ----
    // chunk s (1024B, 32 rows): row i at byte i*32 + (hf ^ ((i>>2)&1))*16
    unsigned aW0[12][4], aW1[12][4];   // layer-0 A fragments, chunks 0..11 (RF)
    {
        const int kb = (w & 3) * 256;
        const int s_ = lane >> 1, hf = lane & 1;
        const float* base = (w < 4) ? W_ih : W_hh;
#pragma unroll 1
        for (int l = 0; l < 2; l++) {
            const float* Wsrc = base + (long)l * 4096 * 1024;
#pragma unroll
            for (int i = 0; i < 32; i++) {
                int srow = (i >> 3) * 1024 + m * 8 + (i & 7);
                const float* src = Wsrc + (long)srow * 1024 + kb + s_ * 16 + hf * 8;
                float4 f0 = ((const float4*)src)[0];
                float4 f1 = ((const float4*)src)[1];
                __half2 p0 = __floats2half2_rn(f0.x, f0.y);
                __half2 p1 = __floats2half2_rn(f0.z, f0.w);
                __half2 p2 = __floats2half2_rn(f1.x, f1.y);
                __half2 p3 = __floats2half2_rn(f1.z, f1.w);
                uint4 u;
                u.x = *reinterpret_cast<unsigned*>(&p0);
                u.y = *reinterpret_cast<unsigned*>(&p1);
                u.z = *reinterpret_cast<unsigned*>(&p2);
                u.w = *reinterpret_cast<unsigned*>(&p3);
                *reinterpret_cast<uint4*>(
                    W1w + s_ * 1024 + i * 32 + (hf ^ ((i >> 2) & 1)) * 16) = u;
            }
            __syncwarp();
            if (l == 0) {
#pragma unroll
                for (int s = 0; s < 12; s++) {
                    unsigned aB = w1su + s * 1024 + aRow * 32 + aSel16;
                    ldsm4(aW0[s], aB);
                    ldsm4(aW1[s], aB + 512);
                }
                __syncwarp();
#pragma unroll
                for (int q = 0; q < 8; q++)
                    ((uint4*)W0w)[lane + 32 * q] =
                        ((const uint4*)(W1w + 12288))[lane + 32 * q];
                __syncwarp();
            }
        }
    }
    __syncthreads();

    float lossacc = 0.f;

    for (int n = 0; n < T_ * L_; n++) {
        const int t = n >> 1, l = n & 1;
        const bool xside = (w < 4);

        // mask/label prefetch first (independent of flag; overlaps the poll)
        const int gu = m * 8 + w;
        const long mo = ((long)(n * B_ + lane)) * H_ + gu;
        const float hmv = __ldg(h_mask + mo);
        const float cmv = __ldg(c_mask + mo);
        float labv = 0.f;
        long ro = 0;
        if (l == 1) {
            ro = ((long)(lane * T_ + t)) * H_ + gu;
            labv = __ldg(labels + ro);
        }

        // ---- dependency-aware wait: only warp 0 polls; x-warps rendezvous.
        if (xside && n) {
            if (w == 0) {
                const unsigned need = (unsigned)n * NCTA;
                if (lane == 0) {
                    unsigned v;
                    do { v = bar_acquire_ld(); } while (v < need);
                }
                __syncwarp();
            }
            asm volatile("bar.sync 1, 128;" ::: "memory");
        }

        const __half* xsrc = xside ? &g_xin[n & 1][k0][0]
                                   : &g_hst[t & 1][l][k0 - 1024][0];

        float acc0[4][4], acc1[4][4];
#pragma unroll
        for (int j = 0; j < 4; j++)
#pragma unroll
            for (int q = 0; q < 4; q++) { acc0[j][q] = 0.f; acc1[j][q] = 0.f; }

        if (l == 0) {
            switch (m & 3) {
            case 0: gemm_l0<0>(stgsu, w0su, xsrc, aW0, aW1, acc0, acc1,
                               lane, aRow, aCol, aSel16); break;
            case 1: gemm_l0<4>(stgsu, w0su, xsrc, aW0, aW1, acc0, acc1,
                               lane, aRow, aCol, aSel16); break;
            case 2: gemm_l0<8>(stgsu, w0su, xsrc, aW0, aW1, acc0, acc1,
                               lane, aRow, aCol, aSel16); break;
            default: gemm_l0<12>(stgsu, w0su, xsrc, aW0, aW1, acc0, acc1,
                                 lane, aRow, aCol, aSel16); break;
            }
        } else {
            gemm_l1(stgsu, w1su, xsrc, rot1, acc0, acc1, lane, aRow, aCol, aSel16);
        }

        // ---- partials: WARP-LOCAL region (aliases own staging; no pre-sync) ----
        {
            float* pw = (float*)STGw;
#pragma unroll
            for (int f = 0; f < 2; f++) {
                float (*ac)[4] = f ? acc1 : acc0;
#pragma unroll
                for (int j = 0; j < 4; j++) {
                    int r0 = f * 16 + (lane >> 2), col = j * 8 + (lane & 3) * 2;
                    pw[r0 * 33 + col]           = ac[j][0];
                    pw[r0 * 33 + col + 1]       = ac[j][1];
                    pw[(r0 + 8) * 33 + col]     = ac[j][2];
                    pw[(r0 + 8) * 33 + col + 1] = ac[j][3];
                }
            }
        }
        __syncthreads();

        // ---- cell math: thread (u=w, b=lane) ----
        {
            float g[4];
#pragma unroll
            for (int gg = 0; gg < 4; gg++) {
                float ssum = 0.f;
#pragma unroll
                for (int ww = 0; ww < 8; ww++)
                    ssum += ((float*)(sm_ + SM_STG + ww * WSTG))[(gg * 8 + w) * 33 + lane];
                g[gg] = ssum + br[l][gg];
            }
            const int si = (l * 8 + w) * 32 + lane;
            float cold = cst[si], hold = hst[si];
            float ccand = sigm(g[1]) * cold + sigm(g[0]) * tanhfast(g[2]);
            float hcand = sigm(g[3]) * tanhfast(ccand);
            float cn = cmv * cold + (1.f - cmv) * ccand;
            float hn = hmv * hold + (1.f - hmv) * hcand;
            cst[si] = cn;
            hst[si] = hn;
            __half hh = __float2half(hn);
            g_xin[(n + 1) & 1][gu][lane] = hh;
            g_hst[(t & 1) ^ 1][l][gu][lane] = hh;
            if (l == 1) {
                out[ro] = hn;
                float d = hn - labv;
                lossacc += d * d;
            }
        }
        __syncthreads();            // partial reads + h stores complete CTA-wide
        if (tid == 0)
            asm volatile("red.release.gpu.global.add.u32 [%0], %1;\n"
                         :: "l"(&g_bar), "r"(1u));
        // h-side warps of cell n+1 proceed immediately; x-side warps poll next.
    }

    // ---- deterministic loss reduction ----
    red[tid] = lossacc;
    __syncthreads();
    for (int sft = 128; sft > 0; sft >>= 1) {
        if (tid < sft) red[tid] += red[tid + sft];
        __syncthreads();
    }
    if (tid == 0) {
        g_losspart[m] = red[0];
        asm volatile("red.release.gpu.global.add.u32 [%0], %1;\n"
                     :: "l"(&g_bar), "r"(1u));
        if (m == 0 && write_loss) {
            const unsigned need = (unsigned)(T_ * L_ + 1) * NCTA;
            unsigned v;
            do { v = bar_acquire_ld(); } while (v < need);
            float ssum = 0.f;
            for (int i = 0; i < NCTA; i++) ssum += g_losspart[i];
            out[RET_ELEMS] = ssum / (float)RET_ELEMS;
        }
    }
}

// ---------------- launch ----------------
extern "C" void kernel_launch(void* const* d_in, const int* in_sizes, int n_in,
                              void* d_out, int out_size) {
    const float* x      = (const float*)d_in[0];
    const float* h0     = (const float*)d_in[1];
    const float* c0     = (const float*)d_in[2];
    const float* h_mask = (const float*)d_in[3];
    const float* c_mask = (const float*)d_in[4];
    const float* labels = (const float*)d_in[5];
    const float* W_ih   = (const float*)d_in[6];
    const float* W_hh   = (const float*)d_in[7];
    const float* b_ih   = (const float*)d_in[8];
    const float* b_hh   = (const float*)d_in[9];
    float* out = (float*)d_out;

    cudaFuncSetAttribute(lstm_kernel, cudaFuncAttributeMaxDynamicSharedMemorySize,
                         SMEM_TOTAL);

    prep<<<128, 256>>>(x, h0);
    int write_loss = (out_size > RET_ELEMS) ? 1 : 0;
    lstm_kernel<<<NCTA, NTHREADS, SMEM_TOTAL>>>(c0, h0, h_mask, c_mask, labels,
                                                W_ih, W_hh, b_ih, b_hh, out,
                                                write_loss);
}